// round 2
// baseline (speedup 1.0000x reference)
#include <cuda_runtime.h>
#include <math.h>

// Problem constants
#define B_   4
#define N_   1024
#define DM   512
#define H_   8
#define DH_  64
#define DI   2048
#define MROWS (B_*N_)          // 4096
#define QKV3 (3*DM)            // 1536

// ---------------------------------------------------------------------------
// Scratch (device globals — no dynamic allocation allowed)
// ---------------------------------------------------------------------------
__device__ float g_Zn  [MROWS*DM];                 // 8 MB
__device__ float g_q   [B_*H_*N_*DH_];             // 8 MB  [B,H,N,DH]
__device__ float g_k   [B_*H_*N_*DH_];             // 8 MB  [B,H,N,DH]
__device__ float g_vT  [B_*H_*DH_*N_];             // 8 MB  [B,H,DH,N]
__device__ float g_S   [(size_t)B_*H_*N_*N_];      // 128 MB [B,H,N,N]
__device__ float g_attn[MROWS*DM];                 // 8 MB  (leaky_relu applied)
__device__ float g_Z2  [MROWS*DM];                 // 8 MB
__device__ float g_Zn2 [MROWS*DM];                 // 8 MB
__device__ float g_Hid [MROWS*DI];                 // 32 MB

// ---------------------------------------------------------------------------
// LayerNorm: one block per row of 512, 128 threads * 4 floats
// ---------------------------------------------------------------------------
__global__ void ln_kernel(const float* __restrict__ X,
                          const float* __restrict__ g,
                          const float* __restrict__ b,
                          float* __restrict__ Y)
{
    const int row = blockIdx.x;
    const int tid = threadIdx.x;          // 128 threads
    const float4* x4 = reinterpret_cast<const float4*>(X + (size_t)row * DM);
    float4 v = x4[tid];

    float s  = v.x + v.y + v.z + v.w;
    float ss = v.x*v.x + v.y*v.y + v.z*v.z + v.w*v.w;
    #pragma unroll
    for (int o = 16; o; o >>= 1) {
        s  += __shfl_xor_sync(0xffffffffu, s,  o);
        ss += __shfl_xor_sync(0xffffffffu, ss, o);
    }
    __shared__ float sh_s[4], sh_ss[4];
    if ((tid & 31) == 0) { sh_s[tid >> 5] = s; sh_ss[tid >> 5] = ss; }
    __syncthreads();
    s  = sh_s[0]  + sh_s[1]  + sh_s[2]  + sh_s[3];
    ss = sh_ss[0] + sh_ss[1] + sh_ss[2] + sh_ss[3];

    const float mu  = s * (1.0f / DM);
    const float var = ss * (1.0f / DM) - mu * mu;
    const float r   = rsqrtf(var + 1e-5f);

    const float4 gv = reinterpret_cast<const float4*>(g)[tid];
    const float4 bv = reinterpret_cast<const float4*>(b)[tid];
    float4 o;
    o.x = (v.x - mu) * r * gv.x + bv.x;
    o.y = (v.y - mu) * r * gv.y + bv.y;
    o.z = (v.z - mu) * r * gv.z + bv.z;
    o.w = (v.w - mu) * r * gv.w + bv.w;
    reinterpret_cast<float4*>(Y + (size_t)row * DM)[tid] = o;
}

// ---------------------------------------------------------------------------
// Row softmax over 1024 cols + multiply by mask. One block per (b,h,n) row.
// 256 threads * 4 floats.
// ---------------------------------------------------------------------------
__global__ void softmax_kernel(float* __restrict__ S, const float* __restrict__ mask)
{
    const int r   = blockIdx.x;       // [B*H*N)
    const int b   = r >> 13;          // / (H*N)
    const int n   = r & (N_ - 1);
    const int tid = threadIdx.x;      // 256

    float4* row = reinterpret_cast<float4*>(S + (size_t)r * N_);
    const float4* mrow =
        reinterpret_cast<const float4*>(mask + ((size_t)b * N_ + n) * N_);

    float4 v = row[tid];
    float mx = fmaxf(fmaxf(v.x, v.y), fmaxf(v.z, v.w));
    #pragma unroll
    for (int o = 16; o; o >>= 1) mx = fmaxf(mx, __shfl_xor_sync(0xffffffffu, mx, o));
    __shared__ float shm[8];
    if ((tid & 31) == 0) shm[tid >> 5] = mx;
    __syncthreads();
    if (tid < 8) {
        float t = shm[tid];
        #pragma unroll
        for (int o = 4; o; o >>= 1) t = fmaxf(t, __shfl_xor_sync(0xffu, t, o));
        shm[tid] = t;
    }
    __syncthreads();
    mx = shm[0];

    float e0 = __expf(v.x - mx), e1 = __expf(v.y - mx);
    float e2 = __expf(v.z - mx), e3 = __expf(v.w - mx);
    float s = e0 + e1 + e2 + e3;
    #pragma unroll
    for (int o = 16; o; o >>= 1) s += __shfl_xor_sync(0xffffffffu, s, o);
    __shared__ float shs[8];
    if ((tid & 31) == 0) shs[tid >> 5] = s;
    __syncthreads();
    if (tid < 8) {
        float t = shs[tid];
        #pragma unroll
        for (int o = 4; o; o >>= 1) t += __shfl_xor_sync(0xffu, t, o);
        shs[tid] = t;
    }
    __syncthreads();
    const float inv = 1.0f / shs[0];

    float4 m = mrow[tid];
    float4 o4 = make_float4(e0 * inv * m.x, e1 * inv * m.y,
                            e2 * inv * m.z, e3 * inv * m.w);
    row[tid] = o4;
}

// ---------------------------------------------------------------------------
// Register-blocked SGEMM computing C = A (MxK, row-major) * B^T (B is NxK
// row-major), batched over blockIdx.z, with fused epilogues.
//   EPI 1: QKV projection -> scatter into g_q / g_k / g_vT, bias added
//   EPI 2: attention scores -> *1/8 + new_mask - gamma*D, into g_S
//   EPI 3: AV -> leaky_relu, scatter into g_attn
//   EPI 4: + optional bias + residual(e1) -> C
//   EPI 5: + bias, relu -> C
// All dims divide tile sizes exactly (asserted by launch configs).
// ---------------------------------------------------------------------------
template<int BM, int BN, int BK, int TM, int TN, int EPI>
__global__ void __launch_bounds__((BM/TM)*(BN/TN))
gemm_kernel(const float* __restrict__ A, const float* __restrict__ Bm,
            const float* __restrict__ bias, float* __restrict__ C,
            int M, int N, int K,
            const float* __restrict__ e1, const float* __restrict__ e2,
            const float* __restrict__ gptr)
{
    constexpr int THREADS = (BM/TM)*(BN/TN);
    constexpr int AST = BM + 4;
    constexpr int BST = BN + 4;

    const int z = blockIdx.z;
    const float* Ab = A  + (size_t)z * M * K;
    const float* Bb = Bm + (size_t)z * N * K;

    __shared__ float As[BK][AST];
    __shared__ float Bs[BK][BST];

    const int tid  = threadIdx.x;
    const int brow = blockIdx.y * BM;
    const int bcol = blockIdx.x * BN;
    const int tcol = tid % (BN / TN);
    const int trow = tid / (BN / TN);

    float acc[TM][TN];
    #pragma unroll
    for (int i = 0; i < TM; i++)
        #pragma unroll
        for (int j = 0; j < TN; j++) acc[i][j] = 0.0f;

    for (int k0 = 0; k0 < K; k0 += BK) {
        #pragma unroll
        for (int i = tid * 4; i < BM * BK; i += THREADS * 4) {
            const int rr = i / BK, kk = i % BK;
            float4 t = *reinterpret_cast<const float4*>(
                Ab + (size_t)(brow + rr) * K + k0 + kk);
            As[kk + 0][rr] = t.x; As[kk + 1][rr] = t.y;
            As[kk + 2][rr] = t.z; As[kk + 3][rr] = t.w;
        }
        #pragma unroll
        for (int i = tid * 4; i < BN * BK; i += THREADS * 4) {
            const int rr = i / BK, kk = i % BK;
            float4 t = *reinterpret_cast<const float4*>(
                Bb + (size_t)(bcol + rr) * K + k0 + kk);
            Bs[kk + 0][rr] = t.x; Bs[kk + 1][rr] = t.y;
            Bs[kk + 2][rr] = t.z; Bs[kk + 3][rr] = t.w;
        }
        __syncthreads();

        #pragma unroll
        for (int kk = 0; kk < BK; kk++) {
            float ar[TM], br[TN];
            #pragma unroll
            for (int i = 0; i < TM; i += 4) {
                float4 t = *reinterpret_cast<const float4*>(&As[kk][trow * TM + i]);
                ar[i] = t.x; ar[i+1] = t.y; ar[i+2] = t.z; ar[i+3] = t.w;
            }
            #pragma unroll
            for (int j = 0; j < TN; j += 4) {
                float4 t = *reinterpret_cast<const float4*>(&Bs[kk][tcol * TN + j]);
                br[j] = t.x; br[j+1] = t.y; br[j+2] = t.z; br[j+3] = t.w;
            }
            #pragma unroll
            for (int i = 0; i < TM; i++)
                #pragma unroll
                for (int j = 0; j < TN; j++)
                    acc[i][j] = fmaf(ar[i], br[j], acc[i][j]);
        }
        __syncthreads();
    }

    float gam = 0.0f;
    if constexpr (EPI == 2) gam = gptr[0];

    const int rowb = brow + trow * TM;
    const int colb = bcol + tcol * TN;
    #pragma unroll
    for (int i = 0; i < TM; i++) {
        const int row = rowb + i;
        #pragma unroll
        for (int j = 0; j < TN; j++) {
            const int col = colb + j;
            float val = acc[i][j];
            if constexpr (EPI == 1) {
                val += bias[col];
                const int h = col / (3 * DH_);
                const int c = col % (3 * DH_);
                const int bb = row >> 10;
                const int n  = row & (N_ - 1);
                if (c < DH_)
                    g_vT[(((size_t)(bb * H_ + h) * DH_ + c) * N_) + n] = val;
                else if (c < 2 * DH_)
                    g_q[(((size_t)(bb * H_ + h) * N_ + n) * DH_) + (c - DH_)] = val;
                else
                    g_k[(((size_t)(bb * H_ + h) * N_ + n) * DH_) + (c - 2 * DH_)] = val;
            } else if constexpr (EPI == 2) {
                const int bb = z >> 3;
                const size_t mi = ((size_t)bb * N_ + row) * N_ + col;
                g_S[(size_t)z * N_ * N_ + (size_t)row * N_ + col] =
                    val * 0.125f + e1[mi] - gam * e2[mi];
            } else if constexpr (EPI == 3) {
                const int bb = z >> 3, h = z & (H_ - 1);
                const float lr = val > 0.0f ? val : 0.01f * val;
                g_attn[((size_t)(bb * N_ + row)) * DM + h * DH_ + col] = lr;
            } else if constexpr (EPI == 4) {
                if (bias) val += bias[col];
                val += e1[(size_t)row * N + col];
                C[(size_t)row * N + col] = val;
            } else if constexpr (EPI == 5) {
                val += bias[col];
                C[(size_t)row * N + col] = fmaxf(val, 0.0f);
            } else {
                if (bias) val += bias[col];
                C[(size_t)row * N + col] = val;
            }
        }
    }
}

// ---------------------------------------------------------------------------
// Launch
// ---------------------------------------------------------------------------
extern "C" void kernel_launch(void* const* d_in, const int* in_sizes, int n_in,
                              void* d_out, int out_size)
{
    const float* Z        = (const float*)d_in[0];
    const float* Dm       = (const float*)d_in[1];
    const float* new_mask = (const float*)d_in[2];
    const float* mask     = (const float*)d_in[3];
    const float* Wqkv     = (const float*)d_in[4];
    const float* bqkv     = (const float*)d_in[5];
    const float* Wo       = (const float*)d_in[6];
    const float* g1       = (const float*)d_in[7];
    const float* b1       = (const float*)d_in[8];
    const float* g2       = (const float*)d_in[9];
    const float* b2       = (const float*)d_in[10];
    const float* Wp1      = (const float*)d_in[11];
    const float* bp1      = (const float*)d_in[12];
    const float* Wp2      = (const float*)d_in[13];
    const float* bp2      = (const float*)d_in[14];
    const float* gamma    = (const float*)d_in[15];
    float* out = (float*)d_out;

    float *pZn, *pq, *pk, *pvT, *pS, *pattn, *pZ2, *pZn2, *pHid;
    cudaGetSymbolAddress((void**)&pZn,   g_Zn);
    cudaGetSymbolAddress((void**)&pq,    g_q);
    cudaGetSymbolAddress((void**)&pk,    g_k);
    cudaGetSymbolAddress((void**)&pvT,   g_vT);
    cudaGetSymbolAddress((void**)&pS,    g_S);
    cudaGetSymbolAddress((void**)&pattn, g_attn);
    cudaGetSymbolAddress((void**)&pZ2,   g_Z2);
    cudaGetSymbolAddress((void**)&pZn2,  g_Zn2);
    cudaGetSymbolAddress((void**)&pHid,  g_Hid);

    // 1) LN1
    ln_kernel<<<MROWS, 128>>>(Z, g1, b1, pZn);

    // 2) QKV projection: [4096,512] x [1536,512]^T -> scatter q/k/vT
    gemm_kernel<128,128,8,8,8,1><<<dim3(QKV3/128, MROWS/128, 1), 256>>>(
        pZn, Wqkv, bqkv, nullptr, MROWS, QKV3, DM, nullptr, nullptr, nullptr);

    // 3) Scores: per (b,h): [1024,64] x [1024,64]^T, fused mask bias -> g_S
    gemm_kernel<128,128,8,8,8,2><<<dim3(N_/128, N_/128, B_*H_), 256>>>(
        pq, pk, nullptr, nullptr, N_, N_, DH_, new_mask, Dm, gamma);

    // 4) Softmax + mask multiply (in place on g_S)
    softmax_kernel<<<B_*H_*N_, 256>>>(pS, mask);

    // 5) AV: per (b,h): [1024,1024] x [64,1024]^T, leaky_relu -> g_attn
    gemm_kernel<128,64,8,8,4,3><<<dim3(1, N_/128, B_*H_), 256>>>(
        pS, pvT, nullptr, nullptr, N_, DH_, N_, nullptr, nullptr, nullptr);

    // 6) Wo + residual: [4096,512] x [512,512]^T + Z -> g_Z2
    gemm_kernel<128,128,8,8,8,4><<<dim3(DM/128, MROWS/128, 1), 256>>>(
        pattn, Wo, nullptr, pZ2, MROWS, DM, DM, Z, nullptr, nullptr);

    // 7) LN2
    ln_kernel<<<MROWS, 128>>>(pZ2, g2, b2, pZn2);

    // 8) MLP1 + relu: [4096,512] x [2048,512]^T -> g_Hid
    gemm_kernel<128,128,8,8,8,5><<<dim3(DI/128, MROWS/128, 1), 256>>>(
        pZn2, Wp1, bp1, pHid, MROWS, DI, DM, nullptr, nullptr, nullptr);

    // 9) MLP2 + bias + residual Z2 -> out
    gemm_kernel<128,128,8,8,8,4><<<dim3(DM/128, MROWS/128, 1), 256>>>(
        pHid, Wp2, bp2, out, MROWS, DM, DI, pZ2, nullptr, nullptr);
}

// round 4
// speedup vs baseline: 3.1955x; 3.1955x over previous
#include <cuda_runtime.h>
#include <cstdint>
#include <math.h>

// Problem constants
#define B_   4
#define N_   1024
#define DM   512
#define H_   8
#define DH_  64
#define DI   2048
#define MROWS (B_*N_)          // 4096
#define QKV3 (3*DM)            // 1536

// ---------------------------------------------------------------------------
// Scratch (device globals)
// ---------------------------------------------------------------------------
__device__ float g_Zn  [MROWS*DM];
__device__ float g_q   [B_*H_*N_*DH_];             // [B,H,N,DH]
__device__ float g_k   [B_*H_*N_*DH_];             // [B,H,N,DH]
__device__ float g_vT  [B_*H_*DH_*N_];             // [B,H,DH,N]
__device__ float g_S   [(size_t)B_*H_*N_*N_];      // [B,H,N,N]
__device__ float g_attn[MROWS*DM];
__device__ float g_Z2  [MROWS*DM];
__device__ float g_Zn2 [MROWS*DM];
__device__ float g_Hid [MROWS*DI];

// ---------------------------------------------------------------------------
// Helpers
// ---------------------------------------------------------------------------
__device__ __forceinline__ uint32_t smem_u32(const void* p) {
    uint32_t a;
    asm("{ .reg .u64 t; cvta.to.shared.u64 t, %1; cvt.u32.u64 %0, t; }" : "=r"(a) : "l"(p));
    return a;
}
#define CP_ASYNC16(sa, ga) \
    asm volatile("cp.async.cg.shared.global [%0], [%1], 16;" :: "r"(sa), "l"(ga))
#define CP_COMMIT() asm volatile("cp.async.commit_group;" ::: "memory")
template<int Nw> __device__ __forceinline__ void cp_wait() {
    asm volatile("cp.async.wait_group %0;" :: "n"(Nw) : "memory");
}
__device__ __forceinline__ void mma_tf32(float& c0, float& c1, float& c2, float& c3,
                                         uint32_t a0, uint32_t a1, uint32_t a2, uint32_t a3,
                                         uint32_t b0, uint32_t b1) {
    asm volatile(
        "mma.sync.aligned.m16n8k8.row.col.f32.tf32.tf32.f32 "
        "{%0,%1,%2,%3},{%4,%5,%6,%7},{%8,%9},{%0,%1,%2,%3};"
        : "+f"(c0), "+f"(c1), "+f"(c2), "+f"(c3)
        : "r"(a0), "r"(a1), "r"(a2), "r"(a3), "r"(b0), "r"(b1));
}

// ---------------------------------------------------------------------------
// LayerNorm
// ---------------------------------------------------------------------------
__global__ void ln_kernel(const float* __restrict__ X,
                          const float* __restrict__ g,
                          const float* __restrict__ b,
                          float* __restrict__ Y)
{
    const int row = blockIdx.x;
    const int tid = threadIdx.x;
    const float4* x4 = reinterpret_cast<const float4*>(X + (size_t)row * DM);
    float4 v = x4[tid];
    float s  = v.x + v.y + v.z + v.w;
    float ss = v.x*v.x + v.y*v.y + v.z*v.z + v.w*v.w;
    #pragma unroll
    for (int o = 16; o; o >>= 1) {
        s  += __shfl_xor_sync(0xffffffffu, s,  o);
        ss += __shfl_xor_sync(0xffffffffu, ss, o);
    }
    __shared__ float sh_s[4], sh_ss[4];
    if ((tid & 31) == 0) { sh_s[tid >> 5] = s; sh_ss[tid >> 5] = ss; }
    __syncthreads();
    s  = sh_s[0]  + sh_s[1]  + sh_s[2]  + sh_s[3];
    ss = sh_ss[0] + sh_ss[1] + sh_ss[2] + sh_ss[3];
    const float mu  = s * (1.0f / DM);
    const float var = ss * (1.0f / DM) - mu * mu;
    const float r   = rsqrtf(var + 1e-5f);
    const float4 gv = reinterpret_cast<const float4*>(g)[tid];
    const float4 bv = reinterpret_cast<const float4*>(b)[tid];
    float4 o;
    o.x = (v.x - mu) * r * gv.x + bv.x;
    o.y = (v.y - mu) * r * gv.y + bv.y;
    o.z = (v.z - mu) * r * gv.z + bv.z;
    o.w = (v.w - mu) * r * gv.w + bv.w;
    reinterpret_cast<float4*>(Y + (size_t)row * DM)[tid] = o;
}

// ---------------------------------------------------------------------------
// Row softmax + mask multiply
// ---------------------------------------------------------------------------
__global__ void softmax_kernel(float* __restrict__ S, const float* __restrict__ mask)
{
    const int r   = blockIdx.x;
    const int b   = r >> 13;
    const int n   = r & (N_ - 1);
    const int tid = threadIdx.x;
    float4* row = reinterpret_cast<float4*>(S + (size_t)r * N_);
    const float4* mrow =
        reinterpret_cast<const float4*>(mask + ((size_t)b * N_ + n) * N_);
    float4 v = row[tid];
    float mx = fmaxf(fmaxf(v.x, v.y), fmaxf(v.z, v.w));
    #pragma unroll
    for (int o = 16; o; o >>= 1) mx = fmaxf(mx, __shfl_xor_sync(0xffffffffu, mx, o));
    __shared__ float shm[8];
    if ((tid & 31) == 0) shm[tid >> 5] = mx;
    __syncthreads();
    if (tid < 8) {
        float t = shm[tid];
        #pragma unroll
        for (int o = 4; o; o >>= 1) t = fmaxf(t, __shfl_xor_sync(0xffu, t, o));
        shm[tid] = t;
    }
    __syncthreads();
    mx = shm[0];
    float e0 = __expf(v.x - mx), e1 = __expf(v.y - mx);
    float e2 = __expf(v.z - mx), e3 = __expf(v.w - mx);
    float s = e0 + e1 + e2 + e3;
    #pragma unroll
    for (int o = 16; o; o >>= 1) s += __shfl_xor_sync(0xffffffffu, s, o);
    __shared__ float shs[8];
    if ((tid & 31) == 0) shs[tid >> 5] = s;
    __syncthreads();
    if (tid < 8) {
        float t = shs[tid];
        #pragma unroll
        for (int o = 4; o; o >>= 1) t += __shfl_xor_sync(0xffu, t, o);
        shs[tid] = t;
    }
    __syncthreads();
    const float inv = 1.0f / shs[0];
    float4 m = mrow[tid];
    row[tid] = make_float4(e0 * inv * m.x, e1 * inv * m.y,
                           e2 * inv * m.z, e3 * inv * m.w);
}

// ---------------------------------------------------------------------------
// tf32 mma.sync GEMM: C = A(MxK) * B(NxK)^T, batched over z, fused epilogues.
// BM=128, BK=32, BN template. Warp tile 64x32 (4x4 of m16n8k8).
// smem padded stride 36 floats -> conflict-free fragment loads.
//   EPI 1: QKV scatter (+bias)   EPI 2: score bias     EPI 3: leaky_relu scatter
//   EPI 4: +bias? +residual      EPI 5: +bias, relu
// ---------------------------------------------------------------------------
template<int BN, int EPI>
__global__ void __launch_bounds__((BN == 128 ? 256 : 128))
tc_gemm(const float* __restrict__ A, const float* __restrict__ Bm,
        const float* __restrict__ bias, float* __restrict__ C,
        int M, int N, int K,
        const float* __restrict__ e1, const float* __restrict__ e2,
        const float* __restrict__ gptr)
{
    constexpr int WCOLS   = BN / 32;             // 4 or 2
    constexpr int WROWS   = 2;
    constexpr int THREADS = WROWS * WCOLS * 32;  // 256 or 128
    constexpr int LDA     = 36;                  // padded stride (floats)
    constexpr int STG     = (128 + BN) * LDA;    // floats per stage

    extern __shared__ float sm[];

    const int tid  = threadIdx.x;
    const int wid  = tid >> 5;
    const int lane = tid & 31;
    const int g    = lane >> 2;       // group id (0..7)
    const int t    = lane & 3;        // thread-in-group
    const int wr   = (wid / WCOLS) * 64;   // warp row offset in CTA tile
    const int wc   = (wid % WCOLS) * 32;   // warp col offset

    const int z    = blockIdx.z;
    const int brow = blockIdx.y * 128;
    const int bcol = blockIdx.x * BN;
    const float* Ab = A  + (size_t)z * M * K + (size_t)brow * K;
    const float* Bb = Bm + (size_t)z * N * K + (size_t)bcol * K;

    float c[4][4][4];
    #pragma unroll
    for (int i = 0; i < 4; i++)
        #pragma unroll
        for (int j = 0; j < 4; j++)
            #pragma unroll
            for (int r = 0; r < 4; r++) c[i][j][r] = 0.0f;

    const uint32_t smb = smem_u32(sm);

    auto load_stage = [&](int s) {
        const int buf = s & 1;
        const uint32_t as = smb + (uint32_t)(buf * STG) * 4u;
        const uint32_t bs = as + 128u * LDA * 4u;
        const float* ag = Ab + s * 32;
        #pragma unroll
        for (int i = tid; i < 128 * 8; i += THREADS) {
            const int r = i >> 3, q = i & 7;
            CP_ASYNC16(as + (uint32_t)(r * LDA + q * 4) * 4u,
                       ag + (size_t)r * K + q * 4);
        }
        const float* bg = Bb + s * 32;
        #pragma unroll
        for (int i = tid; i < BN * 8; i += THREADS) {
            const int r = i >> 3, q = i & 7;
            CP_ASYNC16(bs + (uint32_t)(r * LDA + q * 4) * 4u,
                       bg + (size_t)r * K + q * 4);
        }
        CP_COMMIT();
    };

    const int S = K / 32;
    load_stage(0);

    for (int s = 0; s < S; s++) {
        cp_wait<0>();
        __syncthreads();
        if (s + 1 < S) load_stage(s + 1);

        const int buf = s & 1;
        const uint32_t* As32 = reinterpret_cast<const uint32_t*>(sm + buf * STG);
        const uint32_t* Bs32 = As32 + 128 * LDA;

        #pragma unroll
        for (int kk = 0; kk < 4; kk++) {
            const int k = kk * 8;
            uint32_t af[4][4];
            #pragma unroll
            for (int mt = 0; mt < 4; mt++) {
                const uint32_t* p0 = As32 + (wr + mt * 16 + g) * LDA + k + t;
                const uint32_t* p1 = p0 + 8 * LDA;
                af[mt][0] = p0[0]; af[mt][1] = p1[0];
                af[mt][2] = p0[4]; af[mt][3] = p1[4];
            }
            uint32_t bf[4][2];
            #pragma unroll
            for (int nt = 0; nt < 4; nt++) {
                const uint32_t* p = Bs32 + (wc + nt * 8 + g) * LDA + k + t;
                bf[nt][0] = p[0]; bf[nt][1] = p[4];
            }
            #pragma unroll
            for (int mt = 0; mt < 4; mt++)
                #pragma unroll
                for (int nt = 0; nt < 4; nt++)
                    mma_tf32(c[mt][nt][0], c[mt][nt][1], c[mt][nt][2], c[mt][nt][3],
                             af[mt][0], af[mt][1], af[mt][2], af[mt][3],
                             bf[nt][0], bf[nt][1]);
        }
        __syncthreads();
    }

    // ---------------- epilogue ----------------
    float gam = 0.0f;
    if constexpr (EPI == 2) gam = gptr[0];

    #pragma unroll
    for (int mt = 0; mt < 4; mt++) {
        #pragma unroll
        for (int half = 0; half < 2; half++) {
            const int row = brow + wr + mt * 16 + g + half * 8;
            #pragma unroll
            for (int nt = 0; nt < 4; nt++) {
                const int col = bcol + wc + nt * 8 + 2 * t;
                float v0 = c[mt][nt][half * 2 + 0];
                float v1 = c[mt][nt][half * 2 + 1];
                if constexpr (EPI == 1) {
                    v0 += bias[col]; v1 += bias[col + 1];
                    const int h  = col / (3 * DH_);
                    const int cc = col % (3 * DH_);
                    const int bb = row >> 10;
                    const int n  = row & (N_ - 1);
                    if (cc < DH_) {
                        float* base = g_vT + ((size_t)(bb * H_ + h) * DH_ + cc) * N_ + n;
                        base[0]  = v0;
                        base[N_] = v1;
                    } else if (cc < 2 * DH_) {
                        *reinterpret_cast<float2*>(
                            g_q + ((size_t)(bb * H_ + h) * N_ + n) * DH_ + (cc - DH_)) =
                            make_float2(v0, v1);
                    } else {
                        *reinterpret_cast<float2*>(
                            g_k + ((size_t)(bb * H_ + h) * N_ + n) * DH_ + (cc - 2 * DH_)) =
                            make_float2(v0, v1);
                    }
                } else if constexpr (EPI == 2) {
                    const size_t mi = ((size_t)(z >> 3) * N_ + row) * N_ + col;
                    float2 nm = *reinterpret_cast<const float2*>(e1 + mi);
                    float2 dd = *reinterpret_cast<const float2*>(e2 + mi);
                    *reinterpret_cast<float2*>(
                        g_S + (size_t)z * N_ * N_ + (size_t)row * N_ + col) =
                        make_float2(v0 * 0.125f + nm.x - gam * dd.x,
                                    v1 * 0.125f + nm.y - gam * dd.y);
                } else if constexpr (EPI == 3) {
                    const int bb = z >> 3, h = z & (H_ - 1);
                    *reinterpret_cast<float2*>(
                        g_attn + ((size_t)(bb * N_ + row)) * DM + h * DH_ + col) =
                        make_float2(v0 > 0.f ? v0 : 0.01f * v0,
                                    v1 > 0.f ? v1 : 0.01f * v1);
                } else if constexpr (EPI == 4) {
                    if (bias) { v0 += bias[col]; v1 += bias[col + 1]; }
                    float2 r2 = *reinterpret_cast<const float2*>(e1 + (size_t)row * N + col);
                    *reinterpret_cast<float2*>(C + (size_t)row * N + col) =
                        make_float2(v0 + r2.x, v1 + r2.y);
                } else {  // EPI 5
                    v0 += bias[col]; v1 += bias[col + 1];
                    *reinterpret_cast<float2*>(C + (size_t)row * N + col) =
                        make_float2(fmaxf(v0, 0.f), fmaxf(v1, 0.f));
                }
            }
        }
    }
}

// ---------------------------------------------------------------------------
// Launch
// ---------------------------------------------------------------------------
extern "C" void kernel_launch(void* const* d_in, const int* in_sizes, int n_in,
                              void* d_out, int out_size)
{
    const float* Z        = (const float*)d_in[0];
    const float* Dm       = (const float*)d_in[1];
    const float* new_mask = (const float*)d_in[2];
    const float* mask     = (const float*)d_in[3];
    const float* Wqkv     = (const float*)d_in[4];
    const float* bqkv     = (const float*)d_in[5];
    const float* Wo       = (const float*)d_in[6];
    const float* g1       = (const float*)d_in[7];
    const float* b1       = (const float*)d_in[8];
    const float* g2       = (const float*)d_in[9];
    const float* b2       = (const float*)d_in[10];
    const float* Wp1      = (const float*)d_in[11];
    const float* bp1      = (const float*)d_in[12];
    const float* Wp2      = (const float*)d_in[13];
    const float* bp2      = (const float*)d_in[14];
    const float* gamma    = (const float*)d_in[15];
    float* out = (float*)d_out;

    float *pZn, *pq, *pk, *pvT, *pS, *pattn, *pZ2, *pZn2, *pHid;
    cudaGetSymbolAddress((void**)&pZn,   g_Zn);
    cudaGetSymbolAddress((void**)&pq,    g_q);
    cudaGetSymbolAddress((void**)&pk,    g_k);
    cudaGetSymbolAddress((void**)&pvT,   g_vT);
    cudaGetSymbolAddress((void**)&pS,    g_S);
    cudaGetSymbolAddress((void**)&pattn, g_attn);
    cudaGetSymbolAddress((void**)&pZ2,   g_Z2);
    cudaGetSymbolAddress((void**)&pZn2,  g_Zn2);
    cudaGetSymbolAddress((void**)&pHid,  g_Hid);

    const int SM128 = 2 * (128 + 128) * 36 * 4;  // 73728
    const int SM64  = 2 * (128 + 64)  * 36 * 4;  // 55296
    cudaFuncSetAttribute(tc_gemm<128,1>, cudaFuncAttributeMaxDynamicSharedMemorySize, SM128);
    cudaFuncSetAttribute(tc_gemm<128,2>, cudaFuncAttributeMaxDynamicSharedMemorySize, SM128);
    cudaFuncSetAttribute(tc_gemm<64,3>,  cudaFuncAttributeMaxDynamicSharedMemorySize, SM64);
    cudaFuncSetAttribute(tc_gemm<128,4>, cudaFuncAttributeMaxDynamicSharedMemorySize, SM128);
    cudaFuncSetAttribute(tc_gemm<128,5>, cudaFuncAttributeMaxDynamicSharedMemorySize, SM128);

    // 1) LN1
    ln_kernel<<<MROWS, 128>>>(Z, g1, b1, pZn);

    // 2) QKV: [4096,512] x [1536,512]^T -> scatter q/k/vT
    tc_gemm<128,1><<<dim3(QKV3/128, MROWS/128, 1), 256, SM128>>>(
        pZn, Wqkv, bqkv, nullptr, MROWS, QKV3, DM, nullptr, nullptr, nullptr);

    // 3) Scores: per (b,h) [1024,64] x [1024,64]^T + mask bias -> g_S
    tc_gemm<128,2><<<dim3(N_/128, N_/128, B_*H_), 256, SM128>>>(
        pq, pk, nullptr, nullptr, N_, N_, DH_, new_mask, Dm, gamma);

    // 4) Softmax * mask (in place)
    softmax_kernel<<<B_*H_*N_, 256>>>(pS, mask);

    // 5) AV: per (b,h) [1024,1024] x [64,1024]^T -> leaky_relu -> g_attn
    tc_gemm<64,3><<<dim3(1, N_/128, B_*H_), 128, SM64>>>(
        pS, pvT, nullptr, nullptr, N_, DH_, N_, nullptr, nullptr, nullptr);

    // 6) Wo + residual
    tc_gemm<128,4><<<dim3(DM/128, MROWS/128, 1), 256, SM128>>>(
        pattn, Wo, nullptr, pZ2, MROWS, DM, DM, Z, nullptr, nullptr);

    // 7) LN2
    ln_kernel<<<MROWS, 128>>>(pZ2, g2, b2, pZn2);

    // 8) MLP1 + relu
    tc_gemm<128,5><<<dim3(DI/128, MROWS/128, 1), 256, SM128>>>(
        pZn2, Wp1, bp1, pHid, MROWS, DI, DM, nullptr, nullptr, nullptr);

    // 9) MLP2 + bias + residual -> out
    tc_gemm<128,4><<<dim3(DM/128, MROWS/128, 1), 256, SM128>>>(
        pHid, Wp2, bp2, out, MROWS, DM, DI, pZ2, nullptr, nullptr);
}